// round 4
// baseline (speedup 1.0000x reference)
#include <cuda_runtime.h>
#include <math.h>

#define BB 128
#define TT 512
#define DD 128
#define HH 384
#define GG 1542
#define HSS 64
#define CK 10
#define NBLK 104        // 26 g-tiles x 4 b-tiles, <=148 SMs -> co-resident
#define KTOT 512        // 128 (x) + 384 (h)

__device__ float g_h[(size_t)TT * BB * HH];
__device__ float g_c[BB * HH];
__device__ float g_xout[BB * GG];
__device__ float g_dist[TT * BB];
__device__ float g_theme[(size_t)TT * BB * HH];
__device__ float g_wct[CK * HH * HH];
__device__ unsigned g_cnt;
__device__ volatile unsigned g_gen;

typedef unsigned long long u64;
__device__ __forceinline__ u64 pk2(float a, float b) {
    u64 r; asm("mov.b64 %0,{%1,%2};" : "=l"(r) : "f"(a), "f"(b)); return r;
}
__device__ __forceinline__ void fma2(u64 &d, u64 a, u64 b) {
    asm("fma.rn.f32x2 %0,%1,%2,%0;" : "+l"(d) : "l"(a), "l"(b));
}
__device__ __forceinline__ float2 up2(u64 v) {
    float2 r; asm("mov.b64 {%0,%1},%2;" : "=f"(r.x), "=f"(r.y) : "l"(v)); return r;
}
__device__ __forceinline__ float sgm(float x) { return 1.f / (1.f + expf(-x)); }

__device__ __forceinline__ void gbar() {
    __syncthreads();
    if (threadIdx.x == 0) {
        unsigned old = g_gen;
        __threadfence();
        if (atomicAdd(&g_cnt, 1u) == NBLK - 1) {
            g_cnt = 0;
            __threadfence();
            g_gen = old + 1;
        } else {
            while (g_gen == old) { }
            __threadfence();
        }
    }
    __syncthreads();
}

// local_dis = softmax(cumsum over window of dist), zeros before t=0
__device__ __forceinline__ void calc_dis(int t, int b, float *dis) {
    float cs = 0.f, c[CK];
    #pragma unroll
    for (int k = 0; k < CK; k++) {
        int s = t - (CK - 1) + k;
        cs += (s >= 0) ? g_dist[s * BB + b] : 0.f;
        c[k] = cs;
    }
    float mx = c[0];
    #pragma unroll
    for (int k = 1; k < CK; k++) mx = fmaxf(mx, c[k]);
    float sum = 0.f;
    #pragma unroll
    for (int k = 0; k < CK; k++) { c[k] = expf(c[k] - mx); sum += c[k]; }
    float is = 1.f / sum;
    #pragma unroll
    for (int k = 0; k < CK; k++) dis[k] = c[k] * is;
}

// Wc[o][i][k] -> g_wct[k][i][o]
__global__ void wct_kernel(const float * __restrict__ Wc) {
    int e = blockIdx.x * 256 + threadIdx.x;
    if (e < CK * HH * HH) {
        int o = e % HH, i = (e / HH) % HH, k = e / (HH * HH);
        g_wct[e] = Wc[((size_t)o * HH + i) * CK + k];
    }
}

// A element: k<128 from x_t, else from h_{t-1} (zeros at t=0)
__device__ __forceinline__ float4 loadA(const float * __restrict__ x, int t, int b, int kg) {
    if (kg < DD) return *(const float4 *)&x[((size_t)b * TT + t) * DD + kg];
    if (t > 0)   return *(const float4 *)&g_h[((size_t)(t - 1) * BB + b) * HH + (kg - DD)];
    float4 z; z.x = z.y = z.z = z.w = 0.f; return z;
}

// Persistent phase-1: per-step GEMM [128b x 512K x 1542g] (weights in SMEM)
// + fused gate nonlinearities / state update, 2 grid barriers per step.
__global__ __launch_bounds__(128, 1) void phase1_kernel(
    const float * __restrict__ x, const float * __restrict__ Wk,
    const float * __restrict__ bk, const float * __restrict__ Wr,
    const float * __restrict__ br)
{
    extern __shared__ float sm[];
    float *Bs = sm;                       // [512][64]
    float *As = sm + KTOT * 64;           // [2][16][33]
    float *bias_s = As + 2 * 16 * 33;     // [64]

    int tid = threadIdx.x, blk = blockIdx.x;
    int gt = blk % 26, bt = blk / 26;
    int g0 = gt * 64, b0 = bt * 32;

    // one-time: preload weight tile (coalesced), bias, zero my c slice
    for (int j = 0; j < 256; j++) {
        int e = tid + j * 128;
        int gg = e & 63, k = e >> 6;
        int g = g0 + gg;
        float v = 0.f;
        if (g < GG) v = (k < DD) ? Wk[(size_t)k * GG + g] : Wr[(size_t)(k - DD) * GG + g];
        Bs[e] = v;
    }
    if (tid < 64) {
        int g = g0 + tid;
        bias_s[tid] = (g < GG)
            ? (bk[g] + br[g] + Wk[(size_t)DD * GG + g] + Wr[(size_t)HH * GG + g]) : 0.f;
    }
    for (int e = blk * 128 + tid; e < BB * HH; e += NBLK * 128) g_c[e] = 0.f;
    __syncthreads();

    int sb = tid >> 2;          // staging: b row 0..31
    int sk = (tid & 3) * 4;     // staging: 4 consecutive k within chunk
    int tx = tid & 7, ty = tid >> 3;   // micro-tile: 8g x 2b

    for (int t = 0; t < TT; t++) {
        u64 acc[2][4];
        #pragma unroll
        for (int r = 0; r < 2; r++)
            #pragma unroll
            for (int c = 0; c < 4; c++) acc[r][c] = 0ull;

        // prologue: chunk 0 -> buf0, prefetch chunk 1
        float4 pr = loadA(x, t, b0 + sb, sk);
        As[(sk + 0) * 33 + sb] = pr.x; As[(sk + 1) * 33 + sb] = pr.y;
        As[(sk + 2) * 33 + sb] = pr.z; As[(sk + 3) * 33 + sb] = pr.w;
        pr = loadA(x, t, b0 + sb, 16 + sk);
        __syncthreads();

        for (int ch = 0; ch < KTOT / 16; ch++) {
            if (ch + 1 < KTOT / 16) {
                float *An = As + ((ch + 1) & 1) * 528;
                An[(sk + 0) * 33 + sb] = pr.x; An[(sk + 1) * 33 + sb] = pr.y;
                An[(sk + 2) * 33 + sb] = pr.z; An[(sk + 3) * 33 + sb] = pr.w;
                if (ch + 2 < KTOT / 16) pr = loadA(x, t, b0 + sb, (ch + 2) * 16 + sk);
            }
            const float *Ac = As + (ch & 1) * 528;
            int k0 = ch * 16;
            #pragma unroll
            for (int kk = 0; kk < 16; kk++) {
                float a0 = Ac[kk * 33 + ty * 2], a1 = Ac[kk * 33 + ty * 2 + 1];
                u64 aa0 = pk2(a0, a0), aa1 = pk2(a1, a1);
                const u64 *bp = (const u64 *)&Bs[(k0 + kk) * 64 + tx * 8];
                u64 v0 = bp[0], v1 = bp[1], v2 = bp[2], v3 = bp[3];
                fma2(acc[0][0], aa0, v0); fma2(acc[0][1], aa0, v1);
                fma2(acc[0][2], aa0, v2); fma2(acc[0][3], aa0, v3);
                fma2(acc[1][0], aa1, v0); fma2(acc[1][1], aa1, v1);
                fma2(acc[1][2], aa1, v2); fma2(acc[1][3], aa1, v3);
            }
            __syncthreads();
        }
        // epilogue: bias + store x_out
        #pragma unroll
        for (int r = 0; r < 2; r++) {
            int b = b0 + ty * 2 + r;
            #pragma unroll
            for (int c = 0; c < 4; c++) {
                float2 v = up2(acc[r][c]);
                int g = g0 + tx * 8 + c * 2;
                if (g < GG)     g_xout[(size_t)b * GG + g]     = v.x + bias_s[tx * 8 + c * 2];
                if (g + 1 < GG) g_xout[(size_t)b * GG + g + 1] = v.y + bias_s[tx * 8 + c * 2 + 1];
            }
        }
        gbar();

        // state update (each thread owns fixed elements -> also owns g_c slots)
        for (int e = blk * 128 + tid; e < BB * HH; e += NBLK * 128) {
            int b = e / HH, i = e - b * HH;
            const float *xo = g_xout + (size_t)b * GG;
            float z0 = xo[0], z1 = xo[1], z2 = xo[2];
            float m = fmaxf(z0, fmaxf(z1, z2));
            float e0 = expf(z0 - m), e1 = expf(z1 - m), e2 = expf(z2 - m);
            float inv = 1.f / (e0 + e1 + e2);
            float fm0 = e0 * inv, fm1 = fm0 + e1 * inv, fm2 = fm1 + e2 * inv;
            float y0 = xo[3], y1 = xo[4], y2 = xo[5];
            float mi = fmaxf(y0, fmaxf(y1, y2));
            float q0 = expf(y0 - mi), q1 = expf(y1 - mi), q2 = expf(y2 - mi);
            float iv = 1.f / (q0 + q1 + q2);
            float im2 = q2 * iv, im1 = im2 + q1 * iv, im0 = im1 + q0 * iv;
            int l = i >> 7;
            float fm = (l == 0) ? fm0 : (l == 1 ? fm1 : fm2);
            float im = (l == 0) ? im0 : (l == 1 ? im1 : im2);
            float fg = sgm(xo[6 + i]);
            float ig = sgm(xo[6 + HH + i]);
            float og = sgm(xo[6 + 2 * HH + i]);
            float ci = tanhf(xo[6 + 3 * HH + i]);
            float ov = fm * im;
            float cn = g_c[e] * (ov * fg + fm - ov) + ci * (ov * ig + im - ov);
            g_c[e] = cn;
            g_h[(size_t)t * BB * HH + e] = og * tanhf(cn);
            if (i == 0) g_dist[t * BB + b] = 1.f - (fm0 + fm1 + fm2) * (1.f / 3.f);
        }
        gbar();
    }
}

// theme = sigmoid(relu(mean_k(local_h) @ Ws + bs) @ Wrs + brs); 8 b rows/block.
__global__ __launch_bounds__(256) void theme_kernel(
    const float * __restrict__ Ws, const float * __restrict__ bs,
    const float * __restrict__ Wrs, const float * __restrict__ brs)
{
    int t = blockIdx.x, b0 = blockIdx.y * 8, tid = threadIdx.x;
    __shared__ float dis_s[8][CK], wm[8][HH], s1[8][HSS];
    if (tid < 8) calc_dis(t, b0 + tid, dis_s[tid]);
    __syncthreads();
    #pragma unroll
    for (int j = 0; j < 12; j++) {
        int e = tid + j * 256, b = e / HH, i = e % HH;
        float a = 0.f;
        #pragma unroll
        for (int k = 0; k < CK; k++) {
            int s = t - (CK - 1) + k;
            if (s >= 0) a += dis_s[b][k] * g_h[((size_t)s * BB + b0 + b) * HH + i];
        }
        wm[b][i] = a * (1.f / CK);
    }
    __syncthreads();
    #pragma unroll
    for (int j = 0; j < 2; j++) {
        int e = tid + j * 256, b = e / HSS, hs = e % HSS;
        float a = 0.f;
        for (int i = 0; i < HH; i++) a += wm[b][i] * Ws[i * HSS + hs];
        s1[b][hs] = fmaxf(a + bs[hs], 0.f);
    }
    __syncthreads();
    #pragma unroll
    for (int j = 0; j < 12; j++) {
        int e = tid + j * 256, b = e / HH, o = e % HH;
        float a = 0.f;
        #pragma unroll
        for (int hs = 0; hs < HSS; hs++) a += s1[b][hs] * Wrs[hs * HH + o];
        g_theme[((size_t)t * BB + b0 + b) * HH + o] = sgm(a + brs[o]);
    }
}

// conv[b,o] = sum_{k,i} dis[b,k]*h_{t-9+k}[b,i]*Wct[k,i,o]; y = theme*(conv+bc) + h_t
__global__ __launch_bounds__(256) void conv_kernel(const float * __restrict__ bc,
                                                   float * __restrict__ out)
{
    int t = blockIdx.x, o0 = blockIdx.y * 128, tid = threadIdx.x;
    int tx = tid & 15, ty = tid >> 4;
    __shared__ float dis_s[BB][CK];
    __shared__ float As[BB][17];
    __shared__ __align__(16) float Bs[16][128];
    if (tid < BB) calc_dis(t, tid, dis_s[tid]);
    __syncthreads();

    u64 acc[8][4];
    #pragma unroll
    for (int r = 0; r < 8; r++)
        #pragma unroll
        for (int c = 0; c < 4; c++) acc[r][c] = 0ull;

    const int NCH = CK * (HH / 16); // 240
    float pa[8], pb[8];
    {
        int s = t - (CK - 1);
        #pragma unroll
        for (int l = 0; l < 8; l++) {
            int e = tid + l * 256;
            pa[l] = (s >= 0) ? g_h[((size_t)s * BB + (e >> 4)) * HH + (e & 15)] : 0.f;
            pb[l] = g_wct[(size_t)(e >> 7) * HH + o0 + (e & 127)];
        }
    }
    for (int ch = 0; ch < NCH; ch++) {
        int k = ch / 24;
        __syncthreads();
        #pragma unroll
        for (int l = 0; l < 8; l++) {
            int e = tid + l * 256;
            As[e >> 4][e & 15] = pa[l] * dis_s[e >> 4][k];
            Bs[e >> 7][e & 127] = pb[l];
        }
        __syncthreads();
        if (ch + 1 < NCH) {
            int k2 = (ch + 1) / 24, i0 = ((ch + 1) % 24) * 16, s = t - (CK - 1) + k2;
            #pragma unroll
            for (int l = 0; l < 8; l++) {
                int e = tid + l * 256;
                pa[l] = (s >= 0) ? g_h[((size_t)s * BB + (e >> 4)) * HH + i0 + (e & 15)] : 0.f;
                pb[l] = g_wct[((size_t)k2 * HH + i0 + (e >> 7)) * HH + o0 + (e & 127)];
            }
        }
        #pragma unroll
        for (int kk = 0; kk < 16; kk++) {
            const u64 *bp = (const u64 *)&Bs[kk][tx * 8];
            u64 v0 = bp[0], v1 = bp[1], v2 = bp[2], v3 = bp[3];
            #pragma unroll
            for (int r = 0; r < 8; r++) {
                float a = As[ty * 8 + r][kk];
                u64 aa = pk2(a, a);
                fma2(acc[r][0], aa, v0); fma2(acc[r][1], aa, v1);
                fma2(acc[r][2], aa, v2); fma2(acc[r][3], aa, v3);
            }
        }
    }
    #pragma unroll
    for (int r = 0; r < 8; r++) {
        int b = ty * 8 + r;
        #pragma unroll
        for (int c = 0; c < 4; c++) {
            float2 v = up2(acc[r][c]);
            #pragma unroll
            for (int l = 0; l < 2; l++) {
                int o = o0 + tx * 8 + c * 2 + l;
                float cv = (l ? v.y : v.x) + bc[o];
                out[((size_t)b * TT + t) * HH + o] =
                    g_theme[((size_t)t * BB + b) * HH + o] * cv +
                    g_h[((size_t)t * BB + b) * HH + o];
            }
        }
    }
}

extern "C" void kernel_launch(void* const* d_in, const int* in_sizes, int n_in,
                              void* d_out, int out_size) {
    const float *x   = (const float *)d_in[0];
    const float *Wk  = (const float *)d_in[2];
    const float *bk  = (const float *)d_in[3];
    const float *Wr  = (const float *)d_in[4];
    const float *br  = (const float *)d_in[5];
    const float *Ws  = (const float *)d_in[6];
    const float *bs  = (const float *)d_in[7];
    const float *Wrs = (const float *)d_in[8];
    const float *brs = (const float *)d_in[9];
    const float *Wc  = (const float *)d_in[10];
    const float *bc  = (const float *)d_in[11];
    float *out = (float *)d_out;

    const int smem_bytes = (KTOT * 64 + 2 * 16 * 33 + 64) * 4;  // 135552
    cudaFuncSetAttribute(phase1_kernel,
                         cudaFuncAttributeMaxDynamicSharedMemorySize, smem_bytes);

    wct_kernel<<<(CK * HH * HH + 255) / 256, 256>>>(Wc);
    phase1_kernel<<<NBLK, 128, smem_bytes>>>(x, Wk, bk, Wr, br);
    theme_kernel<<<dim3(TT, 16), 256>>>(Ws, bs, Wrs, brs);
    conv_kernel<<<dim3(TT, 3), 256>>>(bc, out);
}

// round 5
// speedup vs baseline: 1.5130x; 1.5130x over previous
#include <cuda_runtime.h>
#include <math.h>

#define BB 128
#define TT 512
#define DD 128
#define HH 384
#define GG 1542
#define HSS 64
#define CK 10
#define GT 25           // g-tiles of 64 (25*64=1600 >= 1542)
#define NBLK (GT * 4)   // 100 blocks, all co-resident
#define KTOT 512        // 128 (x) + 384 (h)

__device__ float g_h[(size_t)TT * BB * HH];
__device__ float g_c[BB * HH];
__device__ float g_xout[BB * GG];
__device__ float g_dist[TT * BB];
__device__ float g_theme[(size_t)TT * BB * HH];
__device__ float g_wct[CK * HH * HH];
__device__ unsigned g_cnt;
__device__ volatile unsigned g_gen;

typedef unsigned long long u64;
__device__ __forceinline__ u64 pk2(float a, float b) {
    u64 r; asm("mov.b64 %0,{%1,%2};" : "=l"(r) : "f"(a), "f"(b)); return r;
}
__device__ __forceinline__ void fma2(u64 &d, u64 a, u64 b) {
    asm("fma.rn.f32x2 %0,%1,%2,%0;" : "+l"(d) : "l"(a), "l"(b));
}
__device__ __forceinline__ float2 up2(u64 v) {
    float2 r; asm("mov.b64 {%0,%1},%2;" : "=f"(r.x), "=f"(r.y) : "l"(v)); return r;
}
__device__ __forceinline__ float sgm(float x) { return 1.f / (1.f + expf(-x)); }

__device__ __forceinline__ void gbar() {
    __syncthreads();
    if (threadIdx.x == 0) {
        unsigned old = g_gen;
        __threadfence();
        if (atomicAdd(&g_cnt, 1u) == NBLK - 1) {
            g_cnt = 0;
            __threadfence();
            g_gen = old + 1;
        } else {
            while (g_gen == old) { }
            __threadfence();
        }
    }
    __syncthreads();
}

__device__ __forceinline__ void calc_dis(int t, int b, float *dis) {
    float cs = 0.f, c[CK];
    #pragma unroll
    for (int k = 0; k < CK; k++) {
        int s = t - (CK - 1) + k;
        cs += (s >= 0) ? g_dist[s * BB + b] : 0.f;
        c[k] = cs;
    }
    float mx = c[0];
    #pragma unroll
    for (int k = 1; k < CK; k++) mx = fmaxf(mx, c[k]);
    float sum = 0.f;
    #pragma unroll
    for (int k = 0; k < CK; k++) { c[k] = expf(c[k] - mx); sum += c[k]; }
    float is = 1.f / sum;
    #pragma unroll
    for (int k = 0; k < CK; k++) dis[k] = c[k] * is;
}

// Wc[o][i][k] -> g_wct[k][i][o]
__global__ void wct_kernel(const float * __restrict__ Wc) {
    int e = blockIdx.x * 256 + threadIdx.x;
    if (e < CK * HH * HH) {
        int o = e % HH, i = (e / HH) % HH, k = e / (HH * HH);
        g_wct[e] = Wc[((size_t)o * HH + i) * CK + k];
    }
}

__device__ __forceinline__ float4 loadA(const float * __restrict__ x, int t, int b, int k4) {
    if (k4 < DD) return *(const float4 *)&x[((size_t)b * TT + t) * DD + k4];
    if (t > 0)   return *(const float4 *)&g_h[((size_t)(t - 1) * BB + b) * HH + (k4 - DD)];
    float4 z; z.x = z.y = z.z = z.w = 0.f; return z;
}

// Persistent phase-1. 256 thr/block, split-K (2 halves of 256), tile 32b x 64g.
// SMEM: weights [512][64] (131072B) + A [512][34] (69632B) + bias (256B) ~ 201KB.
__global__ __launch_bounds__(256, 1) void phase1_kernel(
    const float * __restrict__ x, const float * __restrict__ Wk,
    const float * __restrict__ bk, const float * __restrict__ Wr,
    const float * __restrict__ br)
{
    extern __shared__ float sm[];
    float *Bs = sm;                       // [512][64]
    float *As = sm + KTOT * 64;           // [512][34]
    float *bias_s = As + KTOT * 34;       // [64]

    int tid = threadIdx.x, blk = blockIdx.x;
    int gt = blk % GT, bt = blk / GT;
    int g0 = gt * 64, b0 = bt * 32;

    // one-time: weights (zero-padded), bias, zero c
    for (int j = 0; j < 128; j++) {
        int e = tid + j * 256;
        int gg = e & 63, k = e >> 6, g = g0 + gg;
        float v = 0.f;
        if (g < GG) v = (k < DD) ? Wk[(size_t)k * GG + g] : Wr[(size_t)(k - DD) * GG + g];
        Bs[e] = v;
    }
    if (tid < 64) {
        int g = g0 + tid;
        bias_s[tid] = (g < GG)
            ? (bk[g] + br[g] + Wk[(size_t)DD * GG + g] + Wr[(size_t)HH * GG + g]) : 0.f;
    }
    for (int e = blk * 256 + tid; e < BB * HH; e += NBLK * 256) g_c[e] = 0.f;
    __syncthreads();

    int sb = tid >> 3, sj = tid & 7;          // staging: row, f4 lane
    int half = tid >> 7, r = tid & 127;
    int tx = r & 7, ty = r >> 3;              // tx: g-quad pair, ty: b-pair

    for (int t = 0; t < TT; t++) {
        // stage whole A tile [512K][32b] into SMEM (16 float4 per thread)
        #pragma unroll
        for (int j = 0; j < 16; j++) {
            int k4 = (sj + j * 8) * 4;
            float4 v = loadA(x, t, b0 + sb, k4);
            As[(k4 + 0) * 34 + sb] = v.x;
            As[(k4 + 1) * 34 + sb] = v.y;
            As[(k4 + 2) * 34 + sb] = v.z;
            As[(k4 + 3) * 34 + sb] = v.w;
        }
        __syncthreads();

        u64 acc[2][4];
        #pragma unroll
        for (int a = 0; a < 2; a++)
            #pragma unroll
            for (int c = 0; c < 4; c++) acc[a][c] = 0ull;

        int kbeg = half * 256;
        #pragma unroll 8
        for (int kk = kbeg; kk < kbeg + 256; kk++) {
            float2 a = *(const float2 *)&As[kk * 34 + ty * 2];
            ulonglong2 bv0 = *(const ulonglong2 *)&Bs[kk * 64 + tx * 4];
            ulonglong2 bv1 = *(const ulonglong2 *)&Bs[kk * 64 + tx * 4 + 32];
            u64 aa0 = pk2(a.x, a.x), aa1 = pk2(a.y, a.y);
            fma2(acc[0][0], aa0, bv0.x); fma2(acc[0][1], aa0, bv0.y);
            fma2(acc[0][2], aa0, bv1.x); fma2(acc[0][3], aa0, bv1.y);
            fma2(acc[1][0], aa1, bv0.x); fma2(acc[1][1], aa1, bv0.y);
            fma2(acc[1][2], aa1, bv1.x); fma2(acc[1][3], aa1, bv1.y);
        }
        __syncthreads();

        // split-K reduction through SMEM (alias As region)
        u64 *red = (u64 *)As;
        if (half) {
            #pragma unroll
            for (int a = 0; a < 2; a++)
                #pragma unroll
                for (int c = 0; c < 4; c++) red[r * 8 + a * 4 + c] = acc[a][c];
        }
        __syncthreads();
        if (!half) {
            #pragma unroll
            for (int a = 0; a < 2; a++) {
                int b = b0 + ty * 2 + a;
                #pragma unroll
                for (int c = 0; c < 4; c++) {
                    float2 v = up2(acc[a][c]);
                    float2 o = up2(red[r * 8 + a * 4 + c]);
                    int q = c >> 1, p = c & 1;
                    int gg = q * 32 + tx * 4 + p * 2;
                    int g = g0 + gg;
                    if (g < GG)     g_xout[(size_t)b * GG + g]     = v.x + o.x + bias_s[gg];
                    if (g + 1 < GG) g_xout[(size_t)b * GG + g + 1] = v.y + o.y + bias_s[gg + 1];
                }
            }
        }
        gbar();

        // fused state update
        for (int e = blk * 256 + tid; e < BB * HH; e += NBLK * 256) {
            int b = e / HH, i = e - b * HH;
            const float *xo = g_xout + (size_t)b * GG;
            float z0 = xo[0], z1 = xo[1], z2 = xo[2];
            float m = fmaxf(z0, fmaxf(z1, z2));
            float e0 = expf(z0 - m), e1 = expf(z1 - m), e2 = expf(z2 - m);
            float inv = 1.f / (e0 + e1 + e2);
            float fm0 = e0 * inv, fm1 = fm0 + e1 * inv, fm2 = fm1 + e2 * inv;
            float y0 = xo[3], y1 = xo[4], y2 = xo[5];
            float mi = fmaxf(y0, fmaxf(y1, y2));
            float q0 = expf(y0 - mi), q1 = expf(y1 - mi), q2 = expf(y2 - mi);
            float iv = 1.f / (q0 + q1 + q2);
            float im2 = q2 * iv, im1 = im2 + q1 * iv, im0 = im1 + q0 * iv;
            int l = i >> 7;
            float fm = (l == 0) ? fm0 : (l == 1 ? fm1 : fm2);
            float im = (l == 0) ? im0 : (l == 1 ? im1 : im2);
            float fg = sgm(xo[6 + i]);
            float ig = sgm(xo[6 + HH + i]);
            float og = sgm(xo[6 + 2 * HH + i]);
            float ci = tanhf(xo[6 + 3 * HH + i]);
            float ov = fm * im;
            float cn = g_c[e] * (ov * fg + fm - ov) + ci * (ov * ig + im - ov);
            g_c[e] = cn;
            g_h[(size_t)t * BB * HH + e] = og * tanhf(cn);
            if (i == 0) g_dist[t * BB + b] = 1.f - (fm0 + fm1 + fm2) * (1.f / 3.f);
        }
        gbar();
    }
}

// theme = sigmoid(relu(mean_k(local_h) @ Ws + bs) @ Wrs + brs); 8 b rows/block.
__global__ __launch_bounds__(256) void theme_kernel(
    const float * __restrict__ Ws, const float * __restrict__ bs,
    const float * __restrict__ Wrs, const float * __restrict__ brs)
{
    int t = blockIdx.x, b0 = blockIdx.y * 8, tid = threadIdx.x;
    __shared__ float dis_s[8][CK], wm[8][HH], s1[8][HSS];
    if (tid < 8) calc_dis(t, b0 + tid, dis_s[tid]);
    __syncthreads();
    #pragma unroll
    for (int j = 0; j < 12; j++) {
        int e = tid + j * 256, b = e / HH, i = e % HH;
        float a = 0.f;
        #pragma unroll
        for (int k = 0; k < CK; k++) {
            int s = t - (CK - 1) + k;
            if (s >= 0) a += dis_s[b][k] * g_h[((size_t)s * BB + b0 + b) * HH + i];
        }
        wm[b][i] = a * (1.f / CK);
    }
    __syncthreads();
    #pragma unroll
    for (int j = 0; j < 2; j++) {
        int e = tid + j * 256, b = e / HSS, hs = e % HSS;
        float a = 0.f;
        for (int i = 0; i < HH; i++) a += wm[b][i] * Ws[i * HSS + hs];
        s1[b][hs] = fmaxf(a + bs[hs], 0.f);
    }
    __syncthreads();
    #pragma unroll
    for (int j = 0; j < 12; j++) {
        int e = tid + j * 256, b = e / HH, o = e % HH;
        float a = 0.f;
        #pragma unroll
        for (int hs = 0; hs < HSS; hs++) a += s1[b][hs] * Wrs[hs * HH + o];
        g_theme[((size_t)t * BB + b0 + b) * HH + o] = sgm(a + brs[o]);
    }
}

// conv[b,o] = sum_{k,i} dis[b,k]*h[b,i]*Wct[k,i,o]; y = theme*(conv+bc) + h_t
// tile 128b x 128o, micro 8b x 8o (two float4 o-groups), conflict-free LDS.128.
#define CONV_FFMA(COMP)                                                     \
    {                                                                       \
        ulonglong2 b0v = *(const ulonglong2 *)&Bs[kk][tx * 4];              \
        ulonglong2 b1v = *(const ulonglong2 *)&Bs[kk][tx * 4 + 64];         \
        _Pragma("unroll")                                                   \
        for (int rr = 0; rr < 8; rr++) {                                    \
            float av = a4[rr].COMP;                                         \
            u64 aa = pk2(av, av);                                           \
            fma2(acc[rr][0], aa, b0v.x); fma2(acc[rr][1], aa, b0v.y);       \
            fma2(acc[rr][2], aa, b1v.x); fma2(acc[rr][3], aa, b1v.y);       \
        }                                                                   \
        kk++;                                                               \
    }

__global__ __launch_bounds__(256) void conv_kernel(const float * __restrict__ bc,
                                                   float * __restrict__ out)
{
    int t = blockIdx.x, o0 = blockIdx.y * 128, tid = threadIdx.x;
    int tx = tid & 15, ty = tid >> 4;
    __shared__ float dis_s[BB][CK];
    __shared__ __align__(16) float As[BB][20];
    __shared__ __align__(16) float Bs[16][128];
    if (tid < BB) calc_dis(t, tid, dis_s[tid]);
    __syncthreads();

    u64 acc[8][4];
    #pragma unroll
    for (int a = 0; a < 8; a++)
        #pragma unroll
        for (int c = 0; c < 4; c++) acc[a][c] = 0ull;

    const int NCH = CK * (HH / 16);  // 240
    float pa[8], pb[8];
    {
        int s = t - (CK - 1);
        #pragma unroll
        for (int l = 0; l < 8; l++) {
            int e = tid + l * 256;
            pa[l] = (s >= 0) ? g_h[((size_t)s * BB + (e >> 4)) * HH + (e & 15)] : 0.f;
            pb[l] = g_wct[(size_t)(e >> 7) * HH + o0 + (e & 127)];
        }
    }
    for (int ch = 0; ch < NCH; ch++) {
        int k = ch / 24;
        __syncthreads();
        #pragma unroll
        for (int l = 0; l < 8; l++) {
            int e = tid + l * 256;
            As[e >> 4][e & 15] = pa[l] * dis_s[e >> 4][k];
            Bs[e >> 7][e & 127] = pb[l];
        }
        __syncthreads();
        if (ch + 1 < NCH) {
            int k2 = (ch + 1) / 24, i0 = ((ch + 1) % 24) * 16, s = t - (CK - 1) + k2;
            #pragma unroll
            for (int l = 0; l < 8; l++) {
                int e = tid + l * 256;
                pa[l] = (s >= 0) ? g_h[((size_t)s * BB + (e >> 4)) * HH + i0 + (e & 15)] : 0.f;
                pb[l] = g_wct[((size_t)k2 * HH + i0 + (e >> 7)) * HH + o0 + (e & 127)];
            }
        }
        #pragma unroll
        for (int kq = 0; kq < 4; kq++) {
            float4 a4[8];
            #pragma unroll
            for (int rr = 0; rr < 8; rr++)
                a4[rr] = *(const float4 *)&As[ty * 8 + rr][kq * 4];
            int kk = kq * 4;
            CONV_FFMA(x)
            CONV_FFMA(y)
            CONV_FFMA(z)
            CONV_FFMA(w)
        }
    }
    #pragma unroll
    for (int rr = 0; rr < 8; rr++) {
        int b = ty * 8 + rr;
        #pragma unroll
        for (int c = 0; c < 4; c++) {
            float2 v = up2(acc[rr][c]);
            int q = c >> 1, p = c & 1;
            #pragma unroll
            for (int l = 0; l < 2; l++) {
                int o = o0 + q * 64 + tx * 4 + p * 2 + l;
                float cv = (l ? v.y : v.x) + bc[o];
                out[((size_t)b * TT + t) * HH + o] =
                    g_theme[((size_t)t * BB + b) * HH + o] * cv +
                    g_h[((size_t)t * BB + b) * HH + o];
            }
        }
    }
}

extern "C" void kernel_launch(void* const* d_in, const int* in_sizes, int n_in,
                              void* d_out, int out_size) {
    const float *x   = (const float *)d_in[0];
    const float *Wk  = (const float *)d_in[2];
    const float *bk  = (const float *)d_in[3];
    const float *Wr  = (const float *)d_in[4];
    const float *br  = (const float *)d_in[5];
    const float *Ws  = (const float *)d_in[6];
    const float *bs  = (const float *)d_in[7];
    const float *Wrs = (const float *)d_in[8];
    const float *brs = (const float *)d_in[9];
    const float *Wc  = (const float *)d_in[10];
    const float *bc  = (const float *)d_in[11];
    float *out = (float *)d_out;

    const int smem_bytes = (KTOT * 64 + KTOT * 34 + 64) * 4;  // 200960
    cudaFuncSetAttribute(phase1_kernel,
                         cudaFuncAttributeMaxDynamicSharedMemorySize, smem_bytes);

    wct_kernel<<<(CK * HH * HH + 255) / 256, 256>>>(Wc);
    phase1_kernel<<<NBLK, 256, smem_bytes>>>(x, Wk, bk, Wr, br);
    theme_kernel<<<dim3(TT, 16), 256>>>(Ws, bs, Wrs, brs);
    conv_kernel<<<dim3(TT, 3), 256>>>(bc, out);
}